// round 7
// baseline (speedup 1.0000x reference)
#include <cuda_runtime.h>
#include <math.h>

// GWD loss, single fused kernel, 4-stage cp.async pipeline:
//  - 256-row chunks; coalesced 16B cp.async (1 L1tex wavefront per line)
//  - prefetch distance 3 chunks -> DRAM latency fully hidden by pipeline
//  - compute 1 row/thread from smem (stride-5, conflict-free), approx math
//  - block reduce -> g_partials; last finished block reduces, writes mean

#define NBLOCKS  740    // 148 SMs * 5 (smem-limited residency)
#define NTHREADS 256
#define CHUNK    256
#define STAGES   4
#define PRED_F4  320    // CHUNK*5/4
#define TOT_F4   704    // pred 320 + targ 320 + wgt 64

__device__ float g_partials[NBLOCKS];
__device__ unsigned int g_count = 0;

__device__ __forceinline__ float f_sqrt(float x) {
    float r; asm("sqrt.approx.f32 %0, %1;" : "=f"(r) : "f"(x)); return r;
}
__device__ __forceinline__ float f_rsqrt(float x) {
    float r; asm("rsqrt.approx.f32 %0, %1;" : "=f"(r) : "f"(x)); return r;
}
__device__ __forceinline__ float f_rcp(float x) {
    float r; asm("rcp.approx.f32 %0, %1;" : "=f"(r) : "f"(x)); return r;
}
__device__ __forceinline__ float f_lg2(float x) {
    float r; asm("lg2.approx.f32 %0, %1;" : "=f"(r) : "f"(x)); return r;
}

__device__ __forceinline__ void cp16(float4* smem, const float4* gmem) {
    unsigned saddr = (unsigned)__cvta_generic_to_shared(smem);
    asm volatile("cp.async.cg.shared.global [%0], [%1], 16;\n"
                 :: "r"(saddr), "l"(gmem));
}

__device__ __forceinline__ float row_loss(
    float xp, float yp, float wp, float hp, float rp,
    float xt, float yt, float wt, float ht, float rt,
    float wgt)
{
    float dx = xp - xt, dy = yp - yt;
    float xyd = dx * dx + dy * dy;

    float cp, sp, ct, st;
    __sincosf(rp, &sp, &cp);
    __sincosf(rt, &st, &ct);

    float w2p = 0.25f * wp * wp, h2p = 0.25f * hp * hp;
    float w2t = 0.25f * wt * wt, h2t = 0.25f * ht * ht;

    float cp2 = cp * cp, sp2 = sp * sp;
    float ct2 = ct * ct, st2 = st * st;

    float a1 = cp2 * w2p + sp2 * h2p;
    float d1 = sp2 * w2p + cp2 * h2p;
    float b1 = cp * sp * (w2p - h2p);

    float a2 = ct2 * w2t + st2 * h2t;
    float d2 = st2 * w2t + ct2 * h2t;
    float b2 = ct * st * (w2t - h2t);

    float trcross = a1 * a2 + 2.0f * b1 * b2 + d1 * d2;
    float prod4   = fabsf(wp * hp * wt * ht);
    float sqdet   = prod4 * 0.0625f;

    float inner = fmaxf(trcross + 2.0f * sqdet, 0.0f);
    float whr   = (w2p + h2p) + (w2t + h2t) - 2.0f * f_sqrt(inner);

    float dist  = f_sqrt(fmaxf(xyd + whr, 0.0f));
    float inv_scale = f_rsqrt(f_sqrt(prod4));   // prod4^(-1/4)
    dist = dist * inv_scale;

    float ln1p = f_lg2(1.0f + dist) * 0.6931471805599453f;
    float loss = 1.0f - f_rcp(1.0f + ln1p);
    return loss * wgt;
}

__global__ __launch_bounds__(NTHREADS)
void gwd_fused_kernel(const float* __restrict__ pred,
                      const float* __restrict__ target,
                      const float* __restrict__ weight,
                      float* __restrict__ out,
                      int n)
{
    // per stage: [0..319]=pred f4, [320..639]=targ f4, [640..703]=weight f4
    __shared__ float4 s_buf[STAGES][TOT_F4];

    const int tid = threadIdx.x;
    const int nchunks = n / CHUNK;
    float acc = 0.0f;

    auto issue = [&](int c, int b) {
        const float4* gp = (const float4*)(pred   + (long)c * CHUNK * 5);
        const float4* gt = (const float4*)(target + (long)c * CHUNK * 5);
        const float4* gw = (const float4*)(weight + (long)c * CHUNK);
        cp16(&s_buf[b][tid],        &gp[tid]);
        cp16(&s_buf[b][320 + tid],  &gt[tid]);
        if (tid < PRED_F4 - NTHREADS) {                   // 64 threads
            cp16(&s_buf[b][256 + tid],       &gp[256 + tid]);
            cp16(&s_buf[b][320 + 256 + tid], &gt[256 + tid]);
            cp16(&s_buf[b][640 + tid],       &gw[tid]);
        }
    };

    // prologue: issue stages 0..STAGES-2 (commit one group per stage,
    // committing an empty group when past the end keeps counts aligned)
    #pragma unroll
    for (int s = 0; s < STAGES - 1; s++) {
        int cc = blockIdx.x + s * gridDim.x;
        if (cc < nchunks) issue(cc, s);
        asm volatile("cp.async.commit_group;\n" ::: "memory");
    }

    int b = 0;
    for (int c = blockIdx.x; c < nchunks; c += gridDim.x)
    {
        int cn = c + (STAGES - 1) * gridDim.x;
        if (cn < nchunks) issue(cn, (b + STAGES - 1) % STAGES);
        asm volatile("cp.async.commit_group;\n" ::: "memory");
        // <= STAGES-1 groups pending -> group for chunk c is complete
        asm volatile("cp.async.wait_group %0;\n" :: "n"(STAGES - 1) : "memory");
        __syncthreads();   // buffer b visible to all threads

        const float* p = (const float*)&s_buf[b][0]   + 5 * tid;
        const float* t = (const float*)&s_buf[b][320] + 5 * tid;
        const float* w = (const float*)&s_buf[b][640];
        acc += row_loss(p[0], p[1], p[2], p[3], p[4],
                        t[0], t[1], t[2], t[3], t[4], w[tid]);

        __syncthreads();   // done reading buffer b before it is re-issued
        b = (b + 1) % STAGES;
    }

    // tail rows (n % CHUNK): block 0, scalar loads
    int tail_start = nchunks * CHUNK;
    if (blockIdx.x == 0 && tail_start + tid < n) {
        int i = tail_start + tid;
        const float* p = pred + 5 * (long)i;
        const float* t = target + 5 * (long)i;
        acc += row_loss(p[0], p[1], p[2], p[3], p[4],
                        t[0], t[1], t[2], t[3], t[4], weight[i]);
    }

    // block reduction
    __shared__ float s_warp[NTHREADS / 32];
    for (int off = 16; off > 0; off >>= 1)
        acc += __shfl_down_sync(0xFFFFFFFFu, acc, off);
    int lane = tid & 31;
    int wid  = tid >> 5;
    if (lane == 0) s_warp[wid] = acc;
    __syncthreads();

    __shared__ bool s_last;
    if (wid == 0) {
        float v = (lane < NTHREADS / 32) ? s_warp[lane] : 0.0f;
        for (int off = 16; off > 0; off >>= 1)
            v += __shfl_down_sync(0xFFFFFFFFu, v, off);
        if (lane == 0) {
            g_partials[blockIdx.x] = v;
            __threadfence();
            unsigned int done = atomicAdd(&g_count, 1u);
            s_last = (done == gridDim.x - 1);
        }
    }
    __syncthreads();

    if (s_last) {
        float v = 0.0f;
        for (int k = tid; k < NBLOCKS; k += NTHREADS)
            v += g_partials[k];
        for (int off = 16; off > 0; off >>= 1)
            v += __shfl_down_sync(0xFFFFFFFFu, v, off);
        if (lane == 0) s_warp[wid] = v;
        __syncthreads();
        if (wid == 0) {
            float r = (lane < NTHREADS / 32) ? s_warp[lane] : 0.0f;
            for (int off = 16; off > 0; off >>= 1)
                r += __shfl_down_sync(0xFFFFFFFFu, r, off);
            if (lane == 0) {
                out[0] = r / (float)n;
                g_count = 0;   // reset for next graph replay
            }
        }
    }
}

extern "C" void kernel_launch(void* const* d_in, const int* in_sizes, int n_in,
                              void* d_out, int out_size)
{
    const float* pred   = (const float*)d_in[0];
    const float* target = (const float*)d_in[1];
    const float* weight = (const float*)d_in[2];
    float* out = (float*)d_out;

    int n = in_sizes[2];  // weight has N elements

    gwd_fused_kernel<<<NBLOCKS, NTHREADS>>>(pred, target, weight, out, n);
}

// round 8
// speedup vs baseline: 1.1577x; 1.1577x over previous
#include <cuda_runtime.h>
#include <math.h>

// GWD loss, single fused kernel, WARP-PRIVATE double-buffered cp.async pipeline:
//  - each warp owns 128-row chunks: 11 coalesced 16B cp.async per lane
//    (pred 160 f4 + targ 160 f4 + wgt 32 f4), double buffered
//  - NO __syncthreads in hot loop: only __syncwarp -> warps drift freely,
//    DRAM demand is continuous instead of barrier-bursty
//  - 4 rows/lane/iteration from smem (stride-5, conflict-free), approx math
//  - block reduce -> g_partials; last finished block reduces (float4), writes mean

#define NBLOCKS   740    // 148 SMs * 5 (45KB smem/block)
#define NTHREADS  128    // 4 warps
#define NWARPS    4
#define WCHUNK    128    // rows per warp-iteration
#define STAGE_F4  352    // pred 160 + targ 160 + wgt 32

__device__ float g_partials[NBLOCKS];
__device__ unsigned int g_count = 0;

__device__ __forceinline__ float f_sqrt(float x) {
    float r; asm("sqrt.approx.f32 %0, %1;" : "=f"(r) : "f"(x)); return r;
}
__device__ __forceinline__ float f_rsqrt(float x) {
    float r; asm("rsqrt.approx.f32 %0, %1;" : "=f"(r) : "f"(x)); return r;
}
__device__ __forceinline__ float f_rcp(float x) {
    float r; asm("rcp.approx.f32 %0, %1;" : "=f"(r) : "f"(x)); return r;
}
__device__ __forceinline__ float f_lg2(float x) {
    float r; asm("lg2.approx.f32 %0, %1;" : "=f"(r) : "f"(x)); return r;
}

__device__ __forceinline__ void cp16(float4* smem, const float4* gmem) {
    unsigned saddr = (unsigned)__cvta_generic_to_shared(smem);
    asm volatile("cp.async.cg.shared.global [%0], [%1], 16;\n"
                 :: "r"(saddr), "l"(gmem));
}

__device__ __forceinline__ float row_loss(
    float xp, float yp, float wp, float hp, float rp,
    float xt, float yt, float wt, float ht, float rt,
    float wgt)
{
    float dx = xp - xt, dy = yp - yt;
    float xyd = dx * dx + dy * dy;

    float cp, sp, ct, st;
    __sincosf(rp, &sp, &cp);
    __sincosf(rt, &st, &ct);

    float w2p = 0.25f * wp * wp, h2p = 0.25f * hp * hp;
    float w2t = 0.25f * wt * wt, h2t = 0.25f * ht * ht;

    float cp2 = cp * cp, sp2 = sp * sp;
    float ct2 = ct * ct, st2 = st * st;

    float a1 = cp2 * w2p + sp2 * h2p;
    float d1 = sp2 * w2p + cp2 * h2p;
    float b1 = cp * sp * (w2p - h2p);

    float a2 = ct2 * w2t + st2 * h2t;
    float d2 = st2 * w2t + ct2 * h2t;
    float b2 = ct * st * (w2t - h2t);

    float trcross = a1 * a2 + 2.0f * b1 * b2 + d1 * d2;
    float prod4   = fabsf(wp * hp * wt * ht);
    float sqdet   = prod4 * 0.0625f;

    float inner = fmaxf(trcross + 2.0f * sqdet, 0.0f);
    float whr   = (w2p + h2p) + (w2t + h2t) - 2.0f * f_sqrt(inner);

    float dist  = f_sqrt(fmaxf(xyd + whr, 0.0f));
    float inv_scale = f_rsqrt(f_sqrt(prod4));   // prod4^(-1/4)
    dist = dist * inv_scale;

    float ln1p = f_lg2(1.0f + dist) * 0.6931471805599453f;
    float loss = 1.0f - f_rcp(1.0f + ln1p);
    return loss * wgt;
}

__global__ __launch_bounds__(NTHREADS)
void gwd_fused_kernel(const float* __restrict__ pred,
                      const float* __restrict__ target,
                      const float* __restrict__ weight,
                      float* __restrict__ out,
                      int n)
{
    // per warp, per stage: [0..159]=pred f4, [160..319]=targ f4, [320..351]=wgt f4
    __shared__ float4 s_buf[NWARPS][2][STAGE_F4];   // 45,056 B

    const int tid  = threadIdx.x;
    const int lane = tid & 31;
    const int warp = tid >> 5;

    const int gw = blockIdx.x * NWARPS + warp;   // global warp id
    const int W  = gridDim.x * NWARPS;           // total warps
    const int nchunks = n / WCHUNK;              // 15625 for N=2M (exact)

    float acc = 0.0f;

    auto issue = [&](int c, float4* b) {
        const float4* gp  = (const float4*)(pred   + (long)c * WCHUNK * 5);
        const float4* gt  = (const float4*)(target + (long)c * WCHUNK * 5);
        const float4* gwt = (const float4*)(weight + (long)c * WCHUNK);
        #pragma unroll
        for (int k = 0; k < 5; k++)
            cp16(&b[k * 32 + lane], &gp[k * 32 + lane]);
        #pragma unroll
        for (int k = 0; k < 5; k++)
            cp16(&b[160 + k * 32 + lane], &gt[k * 32 + lane]);
        cp16(&b[320 + lane], &gwt[lane]);
    };

    int c = gw;
    if (c < nchunks) issue(c, s_buf[warp][0]);
    asm volatile("cp.async.commit_group;\n" ::: "memory");

    int s = 0;
    for (; c < nchunks; c += W)
    {
        int cn = c + W;
        float4* cur = s_buf[warp][s];
        float4* nxt = s_buf[warp][s ^ 1];
        if (cn < nchunks) issue(cn, nxt);
        asm volatile("cp.async.commit_group;\n" ::: "memory");
        asm volatile("cp.async.wait_group 1;\n" ::: "memory");
        __syncwarp();   // cross-lane visibility of cur

        const float* base = (const float*)cur;
        #pragma unroll
        for (int k = 0; k < 4; k++) {
            int r = k * 32 + lane;                 // conflict-free stride-5
            const float* p = base + 5 * r;
            const float* t = base + 640 + 5 * r;
            float wgt = base[1280 + r];
            acc += row_loss(p[0], p[1], p[2], p[3], p[4],
                            t[0], t[1], t[2], t[3], t[4], wgt);
        }
        __syncwarp();   // done reading cur before it's re-issued
        s ^= 1;
    }

    // tail rows (none for N=2M, kept for generality): block 0 scalar
    int tail_start = nchunks * WCHUNK;
    if (blockIdx.x == 0 && tail_start + tid < n) {
        int i = tail_start + tid;
        const float* p = pred + 5 * (long)i;
        const float* t = target + 5 * (long)i;
        acc += row_loss(p[0], p[1], p[2], p[3], p[4],
                        t[0], t[1], t[2], t[3], t[4], weight[i]);
    }

    // block reduction (one barrier total, outside hot loop)
    __shared__ float s_warp[NWARPS];
    for (int off = 16; off > 0; off >>= 1)
        acc += __shfl_down_sync(0xFFFFFFFFu, acc, off);
    if (lane == 0) s_warp[warp] = acc;
    __syncthreads();

    __shared__ bool s_last;
    if (warp == 0) {
        float v = (lane < NWARPS) ? s_warp[lane] : 0.0f;
        for (int off = 2; off > 0; off >>= 1)
            v += __shfl_down_sync(0xFFFFFFFFu, v, off);
        if (lane == 0) {
            g_partials[blockIdx.x] = v;
            __threadfence();
            unsigned int done = atomicAdd(&g_count, 1u);
            s_last = (done == gridDim.x - 1);
        }
    }
    __syncthreads();

    // last block reduces all partials, vectorized (185 f4 = 740 floats)
    if (s_last) {
        const float4* p4 = (const float4*)g_partials;
        float v = 0.0f;
        int nf4 = NBLOCKS / 4;                     // 185
        for (int k = tid; k < nf4; k += NTHREADS) {
            float4 q = p4[k];
            v += (q.x + q.y) + (q.z + q.w);
        }
        for (int off = 16; off > 0; off >>= 1)
            v += __shfl_down_sync(0xFFFFFFFFu, v, off);
        if (lane == 0) s_warp[warp] = v;
        __syncthreads();
        if (warp == 0) {
            float r = (lane < NWARPS) ? s_warp[lane] : 0.0f;
            for (int off = 2; off > 0; off >>= 1)
                r += __shfl_down_sync(0xFFFFFFFFu, r, off);
            if (lane == 0) {
                out[0] = r / (float)n;
                g_count = 0;   // reset for next graph replay
            }
        }
    }
}

extern "C" void kernel_launch(void* const* d_in, const int* in_sizes, int n_in,
                              void* d_out, int out_size)
{
    const float* pred   = (const float*)d_in[0];
    const float* target = (const float*)d_in[1];
    const float* weight = (const float*)d_in[2];
    float* out = (float*)d_out;

    int n = in_sizes[2];  // weight has N elements

    gwd_fused_kernel<<<NBLOCKS, NTHREADS>>>(pred, target, weight, out, n);
}